// round 3
// baseline (speedup 1.0000x reference)
#include <cuda_runtime.h>
#include <math.h>

#define N_Q   6
#define N_CL  32
#define N_MOD 32
#define PART  64
#define B_TOTAL   2048
#define N_CLASSES 150
#define K_FINAL   (N_MOD * N_Q)   // 192
#define FEAT_DIM  2048

#define BT 128  // threads per block in sim kernel

// scratch for per-circuit expectation values: outs[b][p*6+q]
__device__ __align__(16) float g_outs[B_TOTAL * K_FINAL];

__global__ __launch_bounds__(BT, 2) void sim_kernel(
    const float* __restrict__ features,
    const float* __restrict__ Wp,
    const float* __restrict__ bp,
    const float* __restrict__ qw)
{
    __shared__ float s_t[N_CL][N_Q];     // tan(theta/2) per gate
    __shared__ float s_c[N_CL][N_Q];     // (clamped) cos(theta/2) per gate
    __shared__ float s_chunk[8];         // product of c over each 4-layer chunk
    __shared__ float s_Wp[N_Q][PART];
    __shared__ float s_bp[N_Q];

    const int p   = blockIdx.y;                  // module
    const int b   = blockIdx.x * BT + threadIdx.x;
    const int tid = threadIdx.x;

    // cooperative loads: Wp, bp, and this module's layer-gate tan/cos
    for (int i = tid; i < N_Q * PART; i += BT)
        s_Wp[i / PART][i % PART] = Wp[i];
    if (tid < N_Q) s_bp[tid] = bp[tid];
    for (int i = tid; i < N_CL * N_Q; i += BT) {
        float a = qw[p * (N_CL * N_Q) + i];
        float s, c;
        sincosf(0.5f * a, &s, &c);
        float cc = (fabsf(c) < 1e-12f) ? copysignf(1e-12f, c) : c;
        s_t[i / N_Q][i % N_Q] = s / cc;
        s_c[i / N_Q][i % N_Q] = cc;
    }
    __syncthreads();
    if (tid < 8) {
        float prod = 1.0f;
#pragma unroll
        for (int ll = 0; ll < 4; ll++)
#pragma unroll
            for (int q = 0; q < N_Q; q++)
                prod *= s_c[tid * 4 + ll][q];
        s_chunk[tid] = prod;
    }
    __syncthreads();

    // ---- angle projection: angles[q] = <features[b, p*64 : p*64+64], Wp[q]> + bp[q]
    float acc[N_Q];
#pragma unroll
    for (int q = 0; q < N_Q; q++) acc[q] = s_bp[q];
    const float4* fptr = (const float4*)(features + (size_t)b * FEAT_DIM + p * PART);
#pragma unroll
    for (int d4 = 0; d4 < PART / 4; d4++) {
        float4 f = fptr[d4];
#pragma unroll
        for (int q = 0; q < N_Q; q++) {
            acc[q] += f.x * s_Wp[q][d4 * 4 + 0];
            acc[q] += f.y * s_Wp[q][d4 * 4 + 1];
            acc[q] += f.z * s_Wp[q][d4 * 4 + 2];
            acc[q] += f.w * s_Wp[q][d4 * 4 + 3];
        }
    }
    float ca[N_Q], sa[N_Q];
#pragma unroll
    for (int q = 0; q < N_Q; q++) sincosf(0.5f * acc[q], &sa[q], &ca[q]);

    // ---- initial product state (real): sr[i] = prod_q (bit(i,5-q) ? sa[q] : ca[q])
    float sr[64], si[64];
    sr[0] = 1.0f;
#pragma unroll
    for (int q = 0; q < N_Q; q++) {
        const int len = 1 << q;
#pragma unroll
        for (int i = len - 1; i >= 0; i--) {
            float v = sr[i];
            sr[2 * i]     = v * ca[q];
            sr[2 * i + 1] = v * sa[q];
        }
    }
#pragma unroll
    for (int i = 0; i < 64; i++) si[i] = 0.0f;

    // ---- 32 layers: 6x RX (tan form, deferred scale) then CNOT ring.
    //      Rescale by the chunk's cos-product every 4 layers.
    for (int ch = 0; ch < 8; ch++) {
#pragma unroll
        for (int ll = 0; ll < 4; ll++) {
            const int l = ch * 4 + ll;
#pragma unroll
            for (int q = 0; q < N_Q; q++) {
                const float t = s_t[l][q];
                const int bit = 5 - q;       // wire q lives on index bit (5-q)
                const int m   = 1 << bit;
#pragma unroll
                for (int pr = 0; pr < 32; pr++) {
                    const int i0 = ((pr >> bit) << (bit + 1)) | (pr & (m - 1));
                    const int i1 = i0 | m;
                    float r0 = sr[i0], u0 = si[i0];
                    float r1 = sr[i1], u1 = si[i1];
                    // (1/c) * RX: [[1, -i t], [-i t, 1]]
                    sr[i0] = fmaf( t, u1, r0);
                    si[i0] = fmaf(-t, r1, u0);
                    sr[i1] = fmaf( t, u0, r1);
                    si[i1] = fmaf(-t, r0, u1);
                }
            }
            // CNOT ring: ctrl q -> tgt (q+1)%6, applied in order q = 0..5
#pragma unroll
            for (int q = 0; q < N_Q; q++) {
                const int cb = 5 - q;
                const int tb = 5 - ((q + 1) % N_Q);
                const int tm = 1 << tb;
#pragma unroll
                for (int i = 0; i < 64; i++) {
                    if ((((i >> cb) & 1) == 1) && (((i >> tb) & 1) == 0)) {
                        const int j = i | tm;
                        float t2;
                        t2 = sr[i]; sr[i] = sr[j]; sr[j] = t2;
                        t2 = si[i]; si[i] = si[j]; si[j] = t2;
                    }
                }
            }
        }
        const float lam = s_chunk[ch];
#pragma unroll
        for (int i = 0; i < 64; i++) { sr[i] *= lam; si[i] *= lam; }
    }

    // ---- Z expectations: e[q] = sum_i probs[i] * (1 - 2*bit(i,5-q))
    float e[N_Q];
#pragma unroll
    for (int q = 0; q < N_Q; q++) e[q] = 0.0f;
#pragma unroll
    for (int i = 0; i < 64; i++) {
        float pi = sr[i] * sr[i] + si[i] * si[i];
#pragma unroll
        for (int q = 0; q < N_Q; q++) {
            if ((i >> (5 - q)) & 1) e[q] -= pi; else e[q] += pi;
        }
    }

    float* op = g_outs + (size_t)b * K_FINAL + p * N_Q;
#pragma unroll
    for (int q = 0; q < N_Q; q++) op[q] = e[q];
}

// ---------------------------------------------------------------------------
// final linear head as a register-tiled GEMM:
//   out[2048][150] = g_outs[2048][192] @ Wf[150][192]^T + bf
// Block: 8 batch rows, all 150 classes (256 blocks total).
// 240 active threads: each computes 1 row x 5 classes.
// ---------------------------------------------------------------------------
#define FB_M 8                  // batch rows per block
#define FB_K4 (K_FINAL / 4)     // 48 float4 per row

__global__ __launch_bounds__(256) void final_kernel(
    const float* __restrict__ Wf,
    const float* __restrict__ bf,
    float* __restrict__ out)
{
    __shared__ float4 sA[FB_M][FB_K4];   // 8 x 192 floats = 6 KB

    const int tid = threadIdx.x;
    const int b0  = blockIdx.x * FB_M;

    // coalesced load of the A tile (rows are contiguous in g_outs)
    const float4* src = (const float4*)(g_outs + (size_t)b0 * K_FINAL);
    float4* dst = (float4*)sA;
    for (int i = tid; i < FB_M * FB_K4; i += 256)
        dst[i] = src[i];
    __syncthreads();

    if (tid >= 240) return;
    const int row  = tid / 30;        // 0..7
    const int colg = tid % 30;        // 0..29 -> classes colg*5 .. +4

    float acc[5];
#pragma unroll
    for (int n = 0; n < 5; n++) acc[n] = 0.0f;

    const float4* w0 = (const float4*)(Wf + (size_t)(colg * 5) * K_FINAL);

#pragma unroll 4
    for (int k4 = 0; k4 < FB_K4; k4++) {
        float4 av = sA[row][k4];
        float4 wv[5];
#pragma unroll
        for (int n = 0; n < 5; n++)
            wv[n] = __ldg(w0 + (size_t)n * FB_K4 + k4);
#pragma unroll
        for (int n = 0; n < 5; n++) {
            acc[n] += av.x * wv[n].x;
            acc[n] += av.y * wv[n].y;
            acc[n] += av.z * wv[n].z;
            acc[n] += av.w * wv[n].w;
        }
    }

    const int b = b0 + row;
#pragma unroll
    for (int n = 0; n < 5; n++) {
        const int c = colg * 5 + n;
        out[(size_t)b * N_CLASSES + c] = acc[n] + bf[c];
    }
}

extern "C" void kernel_launch(void* const* d_in, const int* in_sizes, int n_in,
                              void* d_out, int out_size)
{
    const float* features = (const float*)d_in[0];
    const float* Wp       = (const float*)d_in[1];
    const float* bp       = (const float*)d_in[2];
    const float* qw       = (const float*)d_in[3];
    const float* Wf       = (const float*)d_in[4];
    const float* bf       = (const float*)d_in[5];
    float* out = (float*)d_out;

    dim3 grid(B_TOTAL / BT, N_MOD);
    sim_kernel<<<grid, BT>>>(features, Wp, bp, qw);
    final_kernel<<<B_TOTAL / FB_M, 256>>>(Wf, bf, out);
}

// round 4
// speedup vs baseline: 1.8435x; 1.8435x over previous
#include <cuda_runtime.h>
#include <math.h>

#define N_Q   6
#define N_CL  32
#define N_MOD 32
#define PART  64
#define B_TOTAL   2048
#define N_CLASSES 150
#define K_FINAL   (N_MOD * N_Q)   // 192
#define FEAT_DIM  2048

#define BT 128  // threads per block in sim kernel

typedef unsigned long long u64;

// scratch for per-circuit expectation values: outs[b][p*6+q]
__device__ __align__(16) float g_outs[B_TOTAL * K_FINAL];

// ---- packed f32x2 helpers (Blackwell FFMA2 path) ----
__device__ __forceinline__ u64 fma2(u64 a, u64 b, u64 c) {
    u64 d;
    asm("fma.rn.f32x2 %0, %1, %2, %3;" : "=l"(d) : "l"(a), "l"(b), "l"(c));
    return d;
}
__device__ __forceinline__ u64 mul2(u64 a, u64 b) {
    u64 d;
    asm("mul.rn.f32x2 %0, %1, %2;" : "=l"(d) : "l"(a), "l"(b));
    return d;
}
__device__ __forceinline__ u64 pack2(float lo, float hi) {
    u64 d;
    asm("mov.b64 %0, {%1, %2};" : "=l"(d) : "f"(lo), "f"(hi));
    return d;
}
__device__ __forceinline__ void unpack2(u64 d, float& lo, float& hi) {
    asm("mov.b64 {%0, %1}, %2;" : "=f"(lo), "=f"(hi) : "l"(d));
}

__global__ __launch_bounds__(BT, 2) void sim_kernel(
    const float* __restrict__ features,
    const float* __restrict__ Wp,
    const float* __restrict__ bp,
    const float* __restrict__ qw)
{
    __shared__ float s_t[N_CL][N_Q];     // tan(theta/2) per gate
    __shared__ float s_c[N_CL][N_Q];     // (clamped) cos(theta/2) per gate
    __shared__ float s_chunk[8];         // product of c over each 4-layer chunk
    __shared__ float s_Wp[N_Q][PART];
    __shared__ float s_bp[N_Q];

    const int p   = blockIdx.y;                  // module
    const int b   = blockIdx.x * BT + threadIdx.x;
    const int tid = threadIdx.x;

    for (int i = tid; i < N_Q * PART; i += BT)
        s_Wp[i / PART][i % PART] = Wp[i];
    if (tid < N_Q) s_bp[tid] = bp[tid];
    for (int i = tid; i < N_CL * N_Q; i += BT) {
        float a = qw[p * (N_CL * N_Q) + i];
        float s, c;
        sincosf(0.5f * a, &s, &c);
        float cc = (fabsf(c) < 1e-12f) ? copysignf(1e-12f, c) : c;
        s_t[i / N_Q][i % N_Q] = s / cc;
        s_c[i / N_Q][i % N_Q] = cc;
    }
    __syncthreads();
    if (tid < 8) {
        float prod = 1.0f;
#pragma unroll
        for (int ll = 0; ll < 4; ll++)
#pragma unroll
            for (int q = 0; q < N_Q; q++)
                prod *= s_c[tid * 4 + ll][q];
        s_chunk[tid] = prod;
    }
    __syncthreads();

    // ---- angle projection
    float acc[N_Q];
#pragma unroll
    for (int q = 0; q < N_Q; q++) acc[q] = s_bp[q];
    const float4* fptr = (const float4*)(features + (size_t)b * FEAT_DIM + p * PART);
#pragma unroll
    for (int d4 = 0; d4 < PART / 4; d4++) {
        float4 f = fptr[d4];
#pragma unroll
        for (int q = 0; q < N_Q; q++) {
            acc[q] += f.x * s_Wp[q][d4 * 4 + 0];
            acc[q] += f.y * s_Wp[q][d4 * 4 + 1];
            acc[q] += f.z * s_Wp[q][d4 * 4 + 2];
            acc[q] += f.w * s_Wp[q][d4 * 4 + 3];
        }
    }
    float ca[N_Q], sa[N_Q];
#pragma unroll
    for (int q = 0; q < N_Q; q++) sincosf(0.5f * acc[q], &sa[q], &ca[q]);

    // ---- initial product state (real)
    float sr0[64];
    sr0[0] = 1.0f;
#pragma unroll
    for (int q = 0; q < N_Q; q++) {
        const int len = 1 << q;
#pragma unroll
        for (int i = len - 1; i >= 0; i--) {
            float v = sr0[i];
            sr0[2 * i]     = v * ca[q];
            sr0[2 * i + 1] = v * sa[q];
        }
    }
    // pack along amplitude bit 0 (= wire 5): reg k holds lanes (amp 2k, amp 2k+1)
    u64 srp[32], sip[32];
#pragma unroll
    for (int k = 0; k < 32; k++) {
        srp[k] = pack2(sr0[2 * k], sr0[2 * k + 1]);
        sip[k] = pack2(0.0f, 0.0f);
    }

    // ---- 32 layers: 6x RX (tan form, packed) then CNOT ring; rescale per 4 layers
    for (int ch = 0; ch < 8; ch++) {
#pragma unroll
        for (int ll = 0; ll < 4; ll++) {
            const int l = ch * 4 + ll;
            // RX on wires 0..4: packed bit pb = 4-q, both lanes identical structure
#pragma unroll
            for (int q = 0; q < 5; q++) {
                const float t = s_t[l][q];
                const u64 tv  = pack2(t, t);
                const u64 ntv = pack2(-t, -t);
                const int pb = 4 - q;
                const int m  = 1 << pb;
#pragma unroll
                for (int pr = 0; pr < 16; pr++) {
                    const int k0 = ((pr >> pb) << (pb + 1)) | (pr & (m - 1));
                    const int k1 = k0 | m;
                    u64 a = srp[k0], bb = sip[k0], c2 = srp[k1], d2 = sip[k1];
                    srp[k0] = fma2(tv,  d2, a);
                    sip[k0] = fma2(ntv, c2, bb);
                    srp[k1] = fma2(tv,  bb, c2);
                    sip[k1] = fma2(ntv, a,  d2);
                }
            }
            // RX on wire 5 (in-lane): scalar on halves
            {
                const float t = s_t[l][5];
#pragma unroll
                for (int k = 0; k < 32; k++) {
                    float r0, r1, u0, u1;
                    unpack2(srp[k], r0, r1);
                    unpack2(sip[k], u0, u1);
                    srp[k] = pack2(fmaf( t, u1, r0), fmaf( t, u0, r1));
                    sip[k] = pack2(fmaf(-t, r1, u0), fmaf(-t, r0, u1));
                }
            }
            // CNOTs q=0..3: whole-register swaps (ctrl packed bit 4-q, tgt 3-q)
#pragma unroll
            for (int q = 0; q < 4; q++) {
                const int cbp = 4 - q;
                const int tbp = 3 - q;
                const int tm  = 1 << tbp;
#pragma unroll
                for (int k = 0; k < 32; k++) {
                    if ((((k >> cbp) & 1) == 1) && (((k >> tbp) & 1) == 0)) {
                        const int j = k | tm;
                        u64 tt;
                        tt = srp[k]; srp[k] = srp[j]; srp[j] = tt;
                        tt = sip[k]; sip[k] = sip[j]; sip[j] = tt;
                    }
                }
            }
            // CNOT q=4: ctrl = packed bit0, tgt = lane -> swap lanes of odd k
#pragma unroll
            for (int k = 1; k < 32; k += 2) {
                float x, y;
                unpack2(srp[k], x, y); srp[k] = pack2(y, x);
                unpack2(sip[k], x, y); sip[k] = pack2(y, x);
            }
            // CNOT q=5: ctrl = lane, tgt = packed bit4 -> swap hi lanes of (k, k+16)
#pragma unroll
            for (int k = 0; k < 16; k++) {
                float a0, a1, b0, b1;
                unpack2(srp[k], a0, a1); unpack2(srp[k + 16], b0, b1);
                srp[k] = pack2(a0, b1);  srp[k + 16] = pack2(b0, a1);
                unpack2(sip[k], a0, a1); unpack2(sip[k + 16], b0, b1);
                sip[k] = pack2(a0, b1);  sip[k + 16] = pack2(b0, a1);
            }
        }
        const float lam = s_chunk[ch];
        const u64 lamv = pack2(lam, lam);
#pragma unroll
        for (int k = 0; k < 32; k++) {
            srp[k] = mul2(srp[k], lamv);
            sip[k] = mul2(sip[k], lamv);
        }
    }

    // ---- probabilities (packed) then Z expectations
    float pr2[64];
#pragma unroll
    for (int k = 0; k < 32; k++) {
        u64 pp = fma2(srp[k], srp[k], mul2(sip[k], sip[k]));
        unpack2(pp, pr2[2 * k], pr2[2 * k + 1]);
    }
    float e[N_Q];
#pragma unroll
    for (int q = 0; q < N_Q; q++) e[q] = 0.0f;
#pragma unroll
    for (int i = 0; i < 64; i++) {
        float pi = pr2[i];
#pragma unroll
        for (int q = 0; q < N_Q; q++) {
            if ((i >> (5 - q)) & 1) e[q] -= pi; else e[q] += pi;
        }
    }

    float* op = g_outs + (size_t)b * K_FINAL + p * N_Q;
#pragma unroll
    for (int q = 0; q < N_Q; q++) op[q] = e[q];
}

// ---------------------------------------------------------------------------
// final head: out[2048][150] = g_outs[2048][192] @ Wf[150][192]^T + bf
// 128 blocks x 16 rows; both operands staged in smem in k-chunks of 32,
// coalesced loads; thread tile 4 rows x 5 cols; broadcast-friendly mapping.
// ---------------------------------------------------------------------------
#define FB_M 16
#define KC   32                // k-chunk
#define PADW 36                // padded row stride (floats), 16B-aligned

__global__ __launch_bounds__(128) void final_kernel(
    const float* __restrict__ Wf,
    const float* __restrict__ bf,
    float* __restrict__ out)
{
    __shared__ float sA[FB_M][PADW];
    __shared__ float sW[N_CLASSES][PADW];

    const int tid = threadIdx.x;
    const int b0  = blockIdx.x * FB_M;
    const int rowg = tid & 3;        // 0..3 -> rows rowg*4 .. +3
    const int colg = tid >> 2;       // 0..31 (active < 30) -> cols colg*5 .. +4

    float acc[4][5];
#pragma unroll
    for (int m = 0; m < 4; m++)
#pragma unroll
        for (int n = 0; n < 5; n++) acc[m][n] = 0.0f;

    for (int kc = 0; kc < K_FINAL / KC; kc++) {
        // A chunk: 16 rows x 32 floats = 128 float4, one per thread (coalesced)
        {
            const int r = tid >> 3, k4 = tid & 7;
            float4 v = *(const float4*)(g_outs + (size_t)(b0 + r) * K_FINAL + kc * KC + k4 * 4);
            *(float4*)&sA[r][k4 * 4] = v;
        }
        // W chunk: 150 rows x 32 floats = 1200 float4 (coalesced)
        for (int i = tid; i < N_CLASSES * 8; i += 128) {
            const int r = i >> 3, k4 = i & 7;
            float4 v = __ldg((const float4*)(Wf + (size_t)r * K_FINAL + kc * KC + k4 * 4));
            *(float4*)&sW[r][k4 * 4] = v;
        }
        __syncthreads();

        if (colg < 30) {
#pragma unroll
            for (int k4 = 0; k4 < KC / 4; k4++) {
                float4 av[4];
#pragma unroll
                for (int m = 0; m < 4; m++)
                    av[m] = *(const float4*)&sA[rowg * 4 + m][k4 * 4];
                float4 wv[5];
#pragma unroll
                for (int n = 0; n < 5; n++)
                    wv[n] = *(const float4*)&sW[colg * 5 + n][k4 * 4];
#pragma unroll
                for (int m = 0; m < 4; m++)
#pragma unroll
                    for (int n = 0; n < 5; n++) {
                        acc[m][n] += av[m].x * wv[n].x;
                        acc[m][n] += av[m].y * wv[n].y;
                        acc[m][n] += av[m].z * wv[n].z;
                        acc[m][n] += av[m].w * wv[n].w;
                    }
            }
        }
        __syncthreads();
    }

    if (colg < 30) {
#pragma unroll
        for (int n = 0; n < 5; n++) {
            const int c = colg * 5 + n;
            const float bias = bf[c];
#pragma unroll
            for (int m = 0; m < 4; m++) {
                const int b = b0 + rowg * 4 + m;
                out[(size_t)b * N_CLASSES + c] = acc[m][n] + bias;
            }
        }
    }
}

extern "C" void kernel_launch(void* const* d_in, const int* in_sizes, int n_in,
                              void* d_out, int out_size)
{
    const float* features = (const float*)d_in[0];
    const float* Wp       = (const float*)d_in[1];
    const float* bp       = (const float*)d_in[2];
    const float* qw       = (const float*)d_in[3];
    const float* Wf       = (const float*)d_in[4];
    const float* bf       = (const float*)d_in[5];
    float* out = (float*)d_out;

    dim3 grid(B_TOTAL / BT, N_MOD);
    sim_kernel<<<grid, BT>>>(features, Wp, bp, qw);
    final_kernel<<<B_TOTAL / FB_M, 128>>>(Wf, bf, out);
}